// round 11
// baseline (speedup 1.0000x reference)
#include <cuda_runtime.h>
#include <cstdint>

// RationalsModel: out[i] = P(x[i]) / (|x[i] * Q(x[i])| + 1)
//   P = sum_{p=0}^{63} coef[p]      * x^p
//   Q = sum_{p=0}^{63} coef[64 + p] * x^p
//
// R11 (= R10 resubmitted; R10 bench was a broker infra failure, no data).
// Validated fma-pipe model (R7-R9): single shared issue port, FFMA2=3cyc,
// FFMA=2cyc, additive; 8 FFMA2/step = 41.9K cyc = 20.9us main is the floor.
// This round removes staging fat: pack (N,D) of ONE element per FFMA2 lane
// pair so the coefficient operand is the natural (coef[p], coef[64+p]) pair
// (2x LDCU.32) and the multiplier is dup2(x) built in-kernel. Pack kernel
// eliminated; graph = 512B D2D memcpy node + main kernel only.

__device__ __forceinline__ uint64_t pack2(float lo, float hi) {
    uint64_t r;
    asm("mov.b64 %0, {%1, %2};" : "=l"(r) : "f"(lo), "f"(hi));
    return r;
}

__device__ __forceinline__ void unpack2(uint64_t v, float& lo, float& hi) {
    asm("mov.b64 {%0, %1}, %2;" : "=f"(lo), "=f"(hi) : "l"(v));
}

// d = a * b + c  (packed 2x f32)
__device__ __forceinline__ uint64_t fma2(uint64_t a, uint64_t b, uint64_t c) {
    uint64_t d;
    asm("fma.rn.f32x2 %0, %1, %2, %3;" : "=l"(d) : "l"(a), "l"(b), "l"(c));
    return d;
}

// Raw copy of coefficients: cC[p] = coef[p] (num), cC[64+p] = coef[64+p] (den).
__constant__ float cC[128];

static constexpr int THREADS = 128;
static constexpr int ELEMS_PER_THREAD = 8;                          // 8 (N,D) lanes
static constexpr int ELEMS_PER_BLOCK = THREADS * ELEMS_PER_THREAD;  // 1024
static constexpr int F4_PER_BLOCK = ELEMS_PER_BLOCK / 4;            // 256

__global__ __launch_bounds__(THREADS)
void rational_kernel(const float4* __restrict__ x4,
                     float4* __restrict__ out4)
{
    int tid = threadIdx.x;

    int base = blockIdx.x * F4_PER_BLOCK + tid;
    float4 a = x4[base];
    float4 b = x4[base + THREADS];

    float xs[8] = {a.x, a.y, a.z, a.w, b.x, b.y, b.z, b.w};

    // x2[i] = dup2(x_i): multiplier for the (N,D) packed Horner lane.
    uint64_t x2[8];
#pragma unroll
    for (int j = 0; j < 8; j++) x2[j] = pack2(xs[j], xs[j]);

    // acc[i] = (P_horner_i, Q_horner_i)
    uint64_t acc[8];
    {
        uint64_t c63 = pack2(cC[63], cC[127]);
#pragma unroll
        for (int j = 0; j < 8; j++) acc[j] = c63;
    }

    // Dual Horner, fully unrolled: per step ONE (cn,cm) pair (2x LDCU.32)
    // feeding 8 FFMA2 (24 fma-pipe cycles).
#pragma unroll
    for (int p = 62; p >= 0; p--) {
        uint64_t cp = pack2(cC[p], cC[64 + p]);
#pragma unroll
        for (int j = 0; j < 8; j++) {
            acc[j] = fma2(acc[j], x2[j], cp);
        }
    }

    // Epilogue: den = x * Q(x); out = P / (|den| + 1).
    float4 o[2];
    float* of = reinterpret_cast<float*>(o);
#pragma unroll
    for (int j = 0; j < 8; j++) {
        float pn, qd;
        unpack2(acc[j], pn, qd);
        of[j] = __fdividef(pn, fabsf(xs[j] * qd) + 1.0f);
    }

    out4[base] = o[0];
    out4[base + THREADS] = o[1];
}

extern "C" void kernel_launch(void* const* d_in, const int* in_sizes, int n_in,
                              void* d_out, int out_size) {
    const float* x    = (const float*)d_in[0];
    const float* coef = (const float*)d_in[1];
    float* out        = (float*)d_out;

    int N = in_sizes[0];                 // 4194304, divisible by 1024
    int blocks = N / ELEMS_PER_BLOCK;    // 4096

    // Single staging node: raw coefficients -> constant memory (D2D, 512B).
    cudaMemcpyToSymbolAsync(cC, coef, 128 * sizeof(float), 0,
                            cudaMemcpyDeviceToDevice, 0);

    rational_kernel<<<blocks, THREADS>>>(
        (const float4*)x, (float4*)out);
}

// round 12
// speedup vs baseline: 1.3138x; 1.3138x over previous
#include <cuda_runtime.h>
#include <cstdint>

// RationalsModel: out[i] = P(x[i]) / (|x[i] * Q(x[i])| + 1)
//   P = sum_{p=0}^{63} coef[p]      * x^p
//   Q = sum_{p=0}^{63} coef[64 + p] * x^p
//
// R12: R11 regressed to issue-bound (alu=15%) because per-step
// pack2(cC[p],cC[64+p]) cost 2 LDC.32 + 2 MOV. Fix: store constants
// PRE-INTERLEAVED (cCi[2p]=coef[p], cCi[2p+1]=coef[64+p]) so each step's
// (cn,cm) operand is ONE aligned LDC.64 into a register pair, zero movs.
// Interleave built by two cudaMemcpy2DAsync D2D nodes (no pack kernel).
// (N,D)-lane pairing: acc=(P_i,Q_i), mult=dup2(x_i), 8 FFMA2/step = the
// validated fma-port floor (~41.9K cyc, 20.9us @2GHz).

__device__ __forceinline__ uint64_t pack2(float lo, float hi) {
    uint64_t r;
    asm("mov.b64 %0, {%1, %2};" : "=l"(r) : "f"(lo), "f"(hi));
    return r;
}

__device__ __forceinline__ void unpack2(uint64_t v, float& lo, float& hi) {
    asm("mov.b64 {%0, %1}, %2;" : "=f"(lo), "=f"(hi) : "l"(v));
}

// d = a * b + c  (packed 2x f32)
__device__ __forceinline__ uint64_t fma2(uint64_t a, uint64_t b, uint64_t c) {
    uint64_t d;
    asm("fma.rn.f32x2 %0, %1, %2, %3;" : "=l"(d) : "l"(a), "l"(b), "l"(c));
    return d;
}

// Interleaved: cCi[2p] = coef[p] (num), cCi[2p+1] = coef[64+p] (den).
// 8-byte aligned so &cCi[2p] is a valid u64 load address.
__constant__ __align__(8) float cCi[128];

static constexpr int THREADS = 128;
static constexpr int ELEMS_PER_THREAD = 8;                          // 8 (N,D) lanes
static constexpr int ELEMS_PER_BLOCK = THREADS * ELEMS_PER_THREAD;  // 1024
static constexpr int F4_PER_BLOCK = ELEMS_PER_BLOCK / 4;            // 256

__global__ __launch_bounds__(THREADS)
void rational_kernel(const float4* __restrict__ x4,
                     float4* __restrict__ out4)
{
    int tid = threadIdx.x;

    int base = blockIdx.x * F4_PER_BLOCK + tid;
    float4 a = x4[base];
    float4 b = x4[base + THREADS];

    float xs[8] = {a.x, a.y, a.z, a.w, b.x, b.y, b.z, b.w};

    // x2[i] = dup2(x_i): multiplier for the (N,D) packed Horner lane.
    uint64_t x2[8];
#pragma unroll
    for (int j = 0; j < 8; j++) x2[j] = pack2(xs[j], xs[j]);

    const uint64_t* cp64 = reinterpret_cast<const uint64_t*>(cCi);

    // acc[i] = (P_horner_i, Q_horner_i)
    uint64_t acc[8];
    {
        uint64_t c63 = cp64[63];   // (coef[63], coef[127]) — one LDC.64
#pragma unroll
        for (int j = 0; j < 8; j++) acc[j] = c63;
    }

    // Dual Horner, fully unrolled: per step ONE LDC.64 (cn,cm) feeding
    // 8 FFMA2 (24 fma-pipe cycles). 9 issues / 24 cycles -> fma-port-bound.
#pragma unroll
    for (int p = 62; p >= 0; p--) {
        uint64_t cp = cp64[p];
#pragma unroll
        for (int j = 0; j < 8; j++) {
            acc[j] = fma2(acc[j], x2[j], cp);
        }
    }

    // Epilogue: den = x * Q(x); out = P / (|den| + 1).
    float4 o[2];
    float* of = reinterpret_cast<float*>(o);
#pragma unroll
    for (int j = 0; j < 8; j++) {
        float pn, qd;
        unpack2(acc[j], pn, qd);
        of[j] = __fdividef(pn, fabsf(xs[j] * qd) + 1.0f);
    }

    out4[base] = o[0];
    out4[base + THREADS] = o[1];
}

extern "C" void kernel_launch(void* const* d_in, const int* in_sizes, int n_in,
                              void* d_out, int out_size) {
    const float* x    = (const float*)d_in[0];
    const float* coef = (const float*)d_in[1];
    float* out        = (float*)d_out;

    int N = in_sizes[0];                 // 4194304, divisible by 1024
    int blocks = N / ELEMS_PER_BLOCK;    // 4096

    // Build the interleaved constant bank with two strided D2D copies:
    //   even slots <- coef[0..63]   (numerator)
    //   odd  slots <- coef[64..127] (denominator)
    void* dst = nullptr;
    cudaGetSymbolAddress(&dst, cCi);
    cudaMemcpy2DAsync(dst, 8, coef, 4,
                      4, 64, cudaMemcpyDeviceToDevice, 0);
    cudaMemcpy2DAsync((char*)dst + 4, 8, coef + 64, 4,
                      4, 64, cudaMemcpyDeviceToDevice, 0);

    rational_kernel<<<blocks, THREADS>>>(
        (const float4*)x, (float4*)out);
}